// round 6
// baseline (speedup 1.0000x reference)
#include <cuda_runtime.h>
#include <cstdint>

// SOM forward: x[128,256] f32, weights[64,64,256] f32
// out = [ bmus(128*2 floats) , diffs(128*64*64*256 floats) ]
//
// R6: L1-wavefront fix. Warp = (2 batches, 8 contiguous neurons): each w row
// is loaded ONCE and reused for both batches -> L1 read wavefronts halved
// (L1 was co-bound with DRAM at ~70%). Two contiguous 8KB write streams per
// warp. Per-lane acc[2][8], deferred interleaved reductions, 2 atomics/warp.
// Single launch; last-block epilogue writes bmus + re-arms globals.

#define B 128
#define D 256
#define MAPM 4096                // 64*64 neurons
#define M_PER_WARP 8
#define B_PER_WARP 2
#define WARPS_PER_BLOCK 8
#define M_PER_BLOCK (M_PER_WARP * WARPS_PER_BLOCK)   // 64
#define MBLOCKS (MAPM / M_PER_BLOCK)                  // 64
#define BBLOCKS (B / B_PER_WARP)                      // 64
#define NBLOCKS (MBLOCKS * BBLOCKS)                   // 4096

__device__ unsigned long long g_best[B];   // zero-init; holds ~min_key
__device__ unsigned int g_done;            // zero-init ticket

__global__ __launch_bounds__(256) void som_fused_kernel(
    const float* __restrict__ x,
    const float* __restrict__ w,
    float* __restrict__ out)   // out = [bmus | diffs]
{
    float* __restrict__ diffs = out + B * 2;

    const int warp = threadIdx.x >> 5;
    const int lane = threadIdx.x & 31;
    const int bp   = blockIdx.x >> 6;                        // 0..63 batch pair
    const int mb   = blockIdx.x & 63;                        // 0..63 m-block
    const int m0   = mb * M_PER_BLOCK + warp * M_PER_WARP;   // warp's first m
    const int b0   = bp * B_PER_WARP;

    // x for both batches in registers (reused across all 8 neurons)
    const float4* __restrict__ xvA = reinterpret_cast<const float4*>(x + (size_t)b0 * D);
    const float4* __restrict__ xvB = reinterpret_cast<const float4*>(x + (size_t)(b0 + 1) * D);
    const float4 xA0 = xvA[lane];
    const float4 xA1 = xvA[32 + lane];
    const float4 xB0 = xvB[lane];
    const float4 xB1 = xvB[32 + lane];

    const float4* __restrict__ wv =
        reinterpret_cast<const float4*>(w + (size_t)m0 * D);
    float4* __restrict__ ovA =
        reinterpret_cast<float4*>(diffs + ((size_t)b0 * MAPM + m0) * D);
    float4* __restrict__ ovB = ovA + (size_t)MAPM * D / 4;   // batch b0+1

    float accA[M_PER_WARP];
    float accB[M_PER_WARP];

    // 1-deep software pipeline on the w row
    float4 wn0 = wv[lane];
    float4 wn1 = wv[32 + lane];

#pragma unroll
    for (int i = 0; i < M_PER_WARP; i++) {
        float4 wa0 = wn0, wa1 = wn1;
        if (i + 1 < M_PER_WARP) {
            wn0 = wv[(i + 1) * 64 + lane];       // contiguous next w row
            wn1 = wv[(i + 1) * 64 + 32 + lane];
        }

        // batch A
        float4 dA0, dA1;
        dA0.x = xA0.x - wa0.x;  dA0.y = xA0.y - wa0.y;
        dA0.z = xA0.z - wa0.z;  dA0.w = xA0.w - wa0.w;
        dA1.x = xA1.x - wa1.x;  dA1.y = xA1.y - wa1.y;
        dA1.z = xA1.z - wa1.z;  dA1.w = xA1.w - wa1.w;
        __stcs(ovA + i * 64 + lane,      dA0);
        __stcs(ovA + i * 64 + 32 + lane, dA1);

        float a;
        a = dA0.x * dA0.x;
        a = fmaf(dA0.y, dA0.y, a);
        a = fmaf(dA0.z, dA0.z, a);
        a = fmaf(dA0.w, dA0.w, a);
        a = fmaf(dA1.x, dA1.x, a);
        a = fmaf(dA1.y, dA1.y, a);
        a = fmaf(dA1.z, dA1.z, a);
        a = fmaf(dA1.w, dA1.w, a);
        accA[i] = a;

        // batch B (same w row — no extra load)
        float4 dB0, dB1;
        dB0.x = xB0.x - wa0.x;  dB0.y = xB0.y - wa0.y;
        dB0.z = xB0.z - wa0.z;  dB0.w = xB0.w - wa0.w;
        dB1.x = xB1.x - wa1.x;  dB1.y = xB1.y - wa1.y;
        dB1.z = xB1.z - wa1.z;  dB1.w = xB1.w - wa1.w;
        __stcs(ovB + i * 64 + lane,      dB0);
        __stcs(ovB + i * 64 + 32 + lane, dB1);

        float bacc;
        bacc = dB0.x * dB0.x;
        bacc = fmaf(dB0.y, dB0.y, bacc);
        bacc = fmaf(dB0.z, dB0.z, bacc);
        bacc = fmaf(dB0.w, dB0.w, bacc);
        bacc = fmaf(dB1.x, dB1.x, bacc);
        bacc = fmaf(dB1.y, dB1.y, bacc);
        bacc = fmaf(dB1.z, dB1.z, bacc);
        bacc = fmaf(dB1.w, dB1.w, bacc);
        accB[i] = bacc;
    }

    // 16 independent warp reductions, interleaved (latency overlapped)
#pragma unroll
    for (int off = 16; off; off >>= 1) {
#pragma unroll
        for (int i = 0; i < M_PER_WARP; i++) {
            accA[i] += __shfl_down_sync(0xffffffffu, accA[i], off);
            accB[i] += __shfl_down_sync(0xffffffffu, accB[i], off);
        }
    }

    if (lane == 0) {
        // local argmin over this warp's 8 neurons, one atomic per batch.
        // key = (d2_bits << 32) | m: u64 min == argmin with lowest-m ties.
        unsigned long long bestA = 0xFFFFFFFFFFFFFFFFULL;
        unsigned long long bestB = 0xFFFFFFFFFFFFFFFFULL;
#pragma unroll
        for (int i = 0; i < M_PER_WARP; i++) {
            unsigned long long kA =
                ((unsigned long long)__float_as_uint(accA[i]) << 32) |
                (unsigned int)(m0 + i);
            unsigned long long kB =
                ((unsigned long long)__float_as_uint(accB[i]) << 32) |
                (unsigned int)(m0 + i);
            bestA = (kA < bestA) ? kA : bestA;
            bestB = (kB < bestB) ? kB : bestB;
        }
        atomicMax(&g_best[b0],     ~bestA);  // min(key) == max(~key)
        atomicMax(&g_best[b0 + 1], ~bestB);
    }

    // ---- last-block epilogue: write bmus, re-arm globals for next replay ----
    __shared__ unsigned int s_last;
    __syncthreads();
    if (threadIdx.x == 0) {
        __threadfence();  // publish this block's g_best updates
        unsigned int ticket = atomicAdd(&g_done, 1);
        s_last = (ticket == NBLOCKS - 1) ? 1u : 0u;
    }
    __syncthreads();
    if (s_last) {
        __threadfence();  // acquire all other blocks' g_best updates
        if (threadIdx.x < B) {
            unsigned long long v = ~g_best[threadIdx.x];
            unsigned int mm = (unsigned int)(v & 0xFFFFFFFFu);
            out[threadIdx.x * 2 + 0] = (float)(mm >> 6);   // row
            out[threadIdx.x * 2 + 1] = (float)(mm & 63);   // col
            g_best[threadIdx.x] = 0ULL;                    // re-arm
        }
        if (threadIdx.x == 0) g_done = 0;                  // re-arm ticket
    }
}

extern "C" void kernel_launch(void* const* d_in, const int* in_sizes, int n_in,
                              void* d_out, int out_size) {
    const float* x = (const float*)d_in[0];
    const float* w = (const float*)d_in[1];
    som_fused_kernel<<<NBLOCKS, 256>>>(x, w, (float*)d_out);
}